// round 3
// baseline (speedup 1.0000x reference)
#include <cuda_runtime.h>

// Problem constants
#define N_TOT 32768   // B*H*W
#define DIM   256
#define KCODE 1024
#define HW    1024    // H*W

// Output layout (floats), concatenated reference tuple:
// z_q_st (8388608) | loss (1) | indices (32768) | new_embedding (262144) | new_cs (1024) | new_es (262144)
#define OFF_ZQ    0
#define OFF_LOSS  8388608
#define OFF_IDX   8388609
#define OFF_NEMB  8421377
#define OFF_NCS   8683521
#define OFF_NES   8684545

// Scratch (device globals: allocation-free)
__device__ float  g_esq[KCODE];
__device__ float  g_zsq[N_TOT];
__device__ int    g_idx[N_TOT];
__device__ float  g_counts[KCODE];
__device__ float  g_embed_sum[KCODE * DIM];
__device__ double g_loss;
__device__ float  g_cluster_size[KCODE];

// ---------------------------------------------------------------------------
// Zero scratch accumulators (graph replays reuse globals)
// ---------------------------------------------------------------------------
__global__ void k_zero() {
    int i = blockIdx.x * blockDim.x + threadIdx.x;
    if (i < KCODE * DIM) g_embed_sum[i] = 0.0f;
    if (i < KCODE)       g_counts[i]    = 0.0f;
    if (i == 0)          g_loss         = 0.0;
}

// ---------------------------------------------------------------------------
// e_sq[k] = ||embedding[k]||^2   (one warp per row; order-insensitive: esq is
// ~8e-5 added onto a ~256-magnitude value, sub-ulp error here is irrelevant)
// ---------------------------------------------------------------------------
__global__ void k_esq(const float* __restrict__ emb) {
    int warp = threadIdx.x >> 5, lane = threadIdx.x & 31;
    int k = blockIdx.x * 8 + warp;
    if (k >= KCODE) return;
    const float* e = emb + k * DIM;
    float s = 0.0f;
    #pragma unroll
    for (int d = lane; d < DIM; d += 32) { float v = e[d]; s = fmaf(v, v, s); }
    #pragma unroll
    for (int o = 16; o; o >>= 1) s += __shfl_xor_sync(0xffffffffu, s, o);
    if (lane == 0) g_esq[k] = s;
}

// ---------------------------------------------------------------------------
// z_sq[n] = ||z_flat[n]||^2, bit-matching a scalar sequential fp32 reduction
// (ascending d, separate mul + add, NO fma). This value's low bits decide the
// rounding of fl(zsq - 2dot) at ulp(256) and hence argmin tie structure.
// ---------------------------------------------------------------------------
__global__ void k_zsq(const float* __restrict__ z) {
    int n = blockIdx.x * blockDim.x + threadIdx.x;
    if (n >= N_TOT) return;
    int b = n >> 10, hw = n & 1023;
    const float* base = z + (size_t)b * (DIM * HW) + hw;
    float s = 0.0f;
    #pragma unroll 8
    for (int d = 0; d < DIM; d++) {
        float v = base[d * HW];
        s = __fadd_rn(s, __fmul_rn(v, v));   // no contraction
    }
    g_zsq[n] = s;
}

// ---------------------------------------------------------------------------
// Fused distance GEMM + argmin.
// Block: 256 threads; tile = 128 rows (n) x 128 cols (k); D in chunks of 32.
// dot accumulated d=0..255 ascending, single fma chain per (n,k) -> bit-matches
// Eigen gebp (sequential-k fma). Score replicates the reference association:
//   s = fl( fl(zsq - 2*dot) + esq )
// Ties resolved to the smallest k (jnp.argmin first-occurrence).
// ---------------------------------------------------------------------------
__launch_bounds__(256, 2)
__global__ void k_argmin(const float* __restrict__ z, const float* __restrict__ emb) {
    __shared__ float z_s[32][129];
    __shared__ float e_s[32][129];
    __shared__ float best_s[128];
    __shared__ int   best_k[128];

    int tid = threadIdx.x;
    int tx = tid & 15, ty = tid >> 4;
    int n0  = blockIdx.x << 7;       // 128-row tile, never crosses a batch (128 | 1024)
    int b   = n0 >> 10;
    int hw0 = n0 & 1023;
    const float* zb = z + (size_t)b * (DIM * HW) + hw0;

    if (tid < 128) { best_s[tid] = 3.4e38f; best_k[tid] = 0; }

    float zsqv[8];
    #pragma unroll
    for (int i = 0; i < 8; i++) zsqv[i] = g_zsq[n0 + ty + 16 * i];

    for (int k0 = 0; k0 < KCODE; k0 += 128) {
        float acc[8][8];
        #pragma unroll
        for (int i = 0; i < 8; i++)
            #pragma unroll
            for (int j = 0; j < 8; j++) acc[i][j] = 0.0f;

        for (int d0 = 0; d0 < DIM; d0 += 32) {
            __syncthreads();
            // z tile: (d0..d0+31) x 128 rows; contiguous in n -> coalesced
            #pragma unroll
            for (int it = 0; it < 16; it++) {
                int idx = tid + it * 256;
                int dl = idx >> 7, r = idx & 127;
                z_s[dl][r] = zb[(d0 + dl) * HW + r];
            }
            // e tile: 128 codes x 32 dims; contiguous in d -> coalesced
            #pragma unroll
            for (int it = 0; it < 16; it++) {
                int idx = tid + it * 256;
                int dl = idx & 31, c = idx >> 5;
                e_s[dl][c] = emb[(k0 + c) * DIM + d0 + dl];
            }
            __syncthreads();
            #pragma unroll
            for (int kk = 0; kk < 32; kk++) {
                float zf[8], ef[8];
                #pragma unroll
                for (int i = 0; i < 8; i++) zf[i] = z_s[kk][ty + 16 * i];
                #pragma unroll
                for (int j = 0; j < 8; j++) ef[j] = e_s[kk][tx + 16 * j];
                #pragma unroll
                for (int i = 0; i < 8; i++)
                    #pragma unroll
                    for (int j = 0; j < 8; j++)
                        acc[i][j] = fmaf(zf[i], ef[j], acc[i][j]);  // sequential-k fma chain
            }
        }

        float esqv[8];
        #pragma unroll
        for (int j = 0; j < 8; j++) esqv[j] = g_esq[k0 + tx + 16 * j];

        #pragma unroll
        for (int i = 0; i < 8; i++) {
            float bs = 3.4e38f; int bk = 0x7fffffff;
            #pragma unroll
            for (int j = 0; j < 8; j++) {
                int kc = k0 + tx + 16 * j;
                // s = fl( fl(zsq - 2*dot) + esq )  -- intrinsics forbid FMA fusion
                float t = __fmul_rn(2.0f, acc[i][j]);        // exact
                float u = __fsub_rn(zsqv[i], t);             // rounds at ulp(~256)
                float s = __fadd_rn(u, esqv[j]);             // rounds again
                if (s < bs || (s == bs && kc < bk)) { bs = s; bk = kc; }
            }
            #pragma unroll
            for (int off = 8; off; off >>= 1) {
                float os = __shfl_xor_sync(0xffffffffu, bs, off);
                int   ok = __shfl_xor_sync(0xffffffffu, bk, off);
                if (os < bs || (os == bs && ok < bk)) { bs = os; bk = ok; }
            }
            if (tx == 0) {
                int r = ty + 16 * i;
                if (bs < best_s[r] || (bs == best_s[r] && bk < best_k[r])) {
                    best_s[r] = bs; best_k[r] = bk;
                }
            }
        }
    }
    __syncthreads();
    if (tid < 128) g_idx[n0 + tid] = best_k[tid];
}

// ---------------------------------------------------------------------------
// Gather z_q, straight-through output, commitment loss, segment sums.
// Element order e = d*32768 + n  (n fastest -> coalesced z / out access).
// z_q_st replicated as fl(z + fl(z_q - z)) to match the reference's rounding.
// ---------------------------------------------------------------------------
__global__ void k_gather(const float* __restrict__ z, const float* __restrict__ emb,
                         float* __restrict__ out) {
    float* out_zq  = out + OFF_ZQ;
    float* out_idx = out + OFF_IDX;
    int tid0 = blockIdx.x * blockDim.x + threadIdx.x;
    int stride = gridDim.x * blockDim.x;
    double lsum = 0.0;
    for (int e = tid0; e < N_TOT * DIM; e += stride) {
        int d = e >> 15;         // /32768
        int n = e & 32767;
        int idx = g_idx[n];
        float zq = emb[idx * DIM + d];
        int b = n >> 10, hw = n & 1023;
        int za = b * (DIM * HW) + d * HW + hw;
        float zv = z[za];
        out_zq[za] = __fadd_rn(zv, __fsub_rn(zq, zv));   // straight-through, 2 roundings
        float df = __fsub_rn(zv, zq);
        lsum += (double)df * (double)df;
        atomicAdd(&g_embed_sum[idx * DIM + d], zv);
        if (d == 0) {
            atomicAdd(&g_counts[idx], 1.0f);
            out_idx[n] = (float)idx;
        }
    }
    // block-reduce loss, one atomic per block
    #pragma unroll
    for (int o = 16; o; o >>= 1) lsum += __shfl_xor_sync(0xffffffffu, lsum, o);
    __shared__ double ws[8];
    int lane = threadIdx.x & 31, warp = threadIdx.x >> 5;
    if (lane == 0) ws[warp] = lsum;
    __syncthreads();
    if (threadIdx.x == 0) {
        double t = 0.0;
        #pragma unroll
        for (int w = 0; w < 8; w++) t += ws[w];
        atomicAdd(&g_loss, t);
    }
}

// ---------------------------------------------------------------------------
// Finalize cluster sizes (1 block of 1024) + loss scalar
// ---------------------------------------------------------------------------
__global__ void k_fin1(const float* __restrict__ ema_cs, float* __restrict__ out) {
    __shared__ float red[1024];
    int k = threadIdx.x;
    const float decay = 0.99f;
    const float one_minus = (float)(1.0 - 0.99);
    float nc = decay * ema_cs[k] + one_minus * g_counts[k];
    red[k] = nc;
    __syncthreads();
    for (int s = 512; s; s >>= 1) {
        if (k < s) red[k] += red[k + s];
        __syncthreads();
    }
    float n = red[0];
    float cs = (nc + 1e-5f) / (n + (float)KCODE * 1e-5f) * n;
    g_cluster_size[k] = cs;
    out[OFF_NCS + k] = nc;
    if (k == 0) out[OFF_LOSS] = (float)(g_loss * (1.0 / 8388608.0));
}

// ---------------------------------------------------------------------------
// Finalize EMA embed sum + new embedding
// ---------------------------------------------------------------------------
__global__ void k_fin2(const float* __restrict__ ema_es, float* __restrict__ out) {
    int i = blockIdx.x * blockDim.x + threadIdx.x;
    if (i >= KCODE * DIM) return;
    const float decay = 0.99f;
    const float one_minus = (float)(1.0 - 0.99);
    float nes = decay * ema_es[i] + one_minus * g_embed_sum[i];
    out[OFF_NES + i] = nes;
    out[OFF_NEMB + i] = nes / g_cluster_size[i >> 8];   // i>>8 = k (DIM=256)
}

// ---------------------------------------------------------------------------
extern "C" void kernel_launch(void* const* d_in, const int* in_sizes, int n_in,
                              void* d_out, int out_size) {
    const float* z      = (const float*)d_in[0];   // (32,256,32,32)
    const float* emb    = (const float*)d_in[1];   // (1024,256)
    const float* ema_cs = (const float*)d_in[2];   // (1024,)
    const float* ema_es = (const float*)d_in[3];   // (1024,256)
    float* out = (float*)d_out;

    k_zero  <<<(KCODE * DIM + 255) / 256 + 1, 256>>>();
    k_esq   <<<KCODE / 8, 256>>>(emb);
    k_zsq   <<<N_TOT / 256, 256>>>(z);
    k_argmin<<<N_TOT / 128, 256>>>(z, emb);
    k_gather<<<2048, 256>>>(z, emb, out);
    k_fin1  <<<1, 1024>>>(ema_cs, out);
    k_fin2  <<<KCODE * DIM / 256, 256>>>(ema_es, out);
}

// round 5
// speedup vs baseline: 1.0346x; 1.0346x over previous
#include <cuda_runtime.h>

// Problem constants
#define N_TOT 32768   // B*H*W
#define DIM   256
#define KCODE 1024
#define HW    1024    // H*W

// Output layout (floats), concatenated reference tuple:
// z_q_st (8388608) | loss (1) | indices (32768) | new_embedding (262144) | new_cs (1024) | new_es (262144)
#define OFF_ZQ    0
#define OFF_LOSS  8388608
#define OFF_IDX   8388609
#define OFF_NEMB  8421377
#define OFF_NCS   8683521
#define OFF_NES   8684545

// Packed fp32x2 FMA (sm_103a FFMA2). Per-lane IEEE RN fma -> bit-identical to
// the scalar fmaf chain, 2 MACs per issued instruction.
#define FFMA2(acc, a, b) \
    asm("fma.rn.f32x2 %0, %1, %2, %0;" : "+l"(acc) : "l"(a), "l"(b))

// Scratch (device globals: allocation-free)
__device__ float  g_esq[KCODE];
__device__ float  g_zsq[N_TOT];
__device__ int    g_idx[N_TOT];
__device__ float  g_counts[KCODE];
__device__ float  g_embed_sum[KCODE * DIM];
__device__ double g_loss;
__device__ float  g_cluster_size[KCODE];

// ---------------------------------------------------------------------------
// Zero scratch accumulators (graph replays reuse globals)
// ---------------------------------------------------------------------------
__global__ void k_zero() {
    int i = blockIdx.x * blockDim.x + threadIdx.x;
    if (i < KCODE * DIM) g_embed_sum[i] = 0.0f;
    if (i < KCODE)       g_counts[i]    = 0.0f;
    if (i == 0)          g_loss         = 0.0;
}

// ---------------------------------------------------------------------------
// e_sq[k] = ||embedding[k]||^2   (one warp per row; esq is ~8e-5 added onto a
// ~256-magnitude value, sub-ulp ordering differences here are irrelevant)
// ---------------------------------------------------------------------------
__global__ void k_esq(const float* __restrict__ emb) {
    int warp = threadIdx.x >> 5, lane = threadIdx.x & 31;
    int k = blockIdx.x * 8 + warp;
    if (k >= KCODE) return;
    const float* e = emb + k * DIM;
    float s = 0.0f;
    #pragma unroll
    for (int d = lane; d < DIM; d += 32) { float v = e[d]; s = fmaf(v, v, s); }
    #pragma unroll
    for (int o = 16; o; o >>= 1) s += __shfl_xor_sync(0xffffffffu, s, o);
    if (lane == 0) g_esq[k] = s;
}

// ---------------------------------------------------------------------------
// z_sq[n] = ||z_flat[n]||^2, bit-matching a scalar sequential fp32 reduction
// (ascending d, separate mul + add, NO fma).
// ---------------------------------------------------------------------------
__global__ void k_zsq(const float* __restrict__ z) {
    int n = blockIdx.x * blockDim.x + threadIdx.x;
    if (n >= N_TOT) return;
    int b = n >> 10, hw = n & 1023;
    const float* base = z + (size_t)b * (DIM * HW) + hw;
    float s = 0.0f;
    #pragma unroll 8
    for (int d = 0; d < DIM; d++) {
        float v = base[d * HW];
        s = __fadd_rn(s, __fmul_rn(v, v));   // no contraction
    }
    g_zsq[n] = s;
}

// ---------------------------------------------------------------------------
// Fused distance GEMM + argmin, FFMA2 (packed fp32x2) edition.
// Block 256 threads; tile 128 rows (n) x 128 cols (k); D in chunks of 16.
// Thread (tx,ty), tx=tid&15, ty=tid>>4:
//   rows  = ty + 16*i            (i = 0..7)
//   cols  = 2*tx + 32*j + {0,1}  (j = 0..3)  -> col pairs are contiguous
// z is stored DUPLICATED in shared (z,z per row slot) so the broadcast operand
// of the packed FMA is a single LDS.64; e col pairs are natural LDS.64.
// Accumulation stays a single fma chain per (n,k), d ascending -> bit-exact.
// ---------------------------------------------------------------------------
__launch_bounds__(256, 2)
__global__ void k_argmin(const float* __restrict__ z, const float* __restrict__ emb) {
    __shared__ __align__(16) float z_dup[16][258];   // [d][2*row] duplicated pairs
    __shared__ __align__(16) float e_s[16][132];     // [d][col]
    __shared__ float best_s[128];
    __shared__ int   best_k[128];

    int tid = threadIdx.x;
    int tx = tid & 15, ty = tid >> 4;
    int n0  = blockIdx.x << 7;       // 128-row tile, never crosses a batch (128 | 1024)
    int b   = n0 >> 10;
    int hw0 = n0 & 1023;
    const float* zb = z + (size_t)b * (DIM * HW) + hw0;

    if (tid < 128) { best_s[tid] = 3.4e38f; best_k[tid] = 0; }

    float zsqv[8];
    #pragma unroll
    for (int i = 0; i < 8; i++) zsqv[i] = g_zsq[n0 + ty + 16 * i];

    for (int k0 = 0; k0 < KCODE; k0 += 128) {
        unsigned long long acc[8][4];    // packed (col 2tx+32j, col 2tx+32j+1)
        #pragma unroll
        for (int i = 0; i < 8; i++)
            #pragma unroll
            for (int j = 0; j < 4; j++) acc[i][j] = 0ull;

        for (int d0 = 0; d0 < DIM; d0 += 16) {
            __syncthreads();
            // z tile: 16 dims x 128 rows, duplicated. 2048 elements / 256 thr.
            #pragma unroll
            for (int it = 0; it < 8; it++) {
                int idx = tid + it * 256;
                int dl = idx >> 7, r = idx & 127;
                float v = zb[(d0 + dl) * HW + r];
                *reinterpret_cast<float2*>(&z_dup[dl][2 * r]) = make_float2(v, v);
            }
            // e tile: 128 cols x 16 dims (dl fastest in gmem -> 64B bursts)
            #pragma unroll
            for (int it = 0; it < 8; it++) {
                int idx = tid + it * 256;
                int dl = idx & 15, c = idx >> 4;
                e_s[dl][c] = emb[(k0 + c) * DIM + d0 + dl];
            }
            __syncthreads();
            #pragma unroll
            for (int kk = 0; kk < 16; kk++) {
                unsigned long long zz[8], ef[4];
                #pragma unroll
                for (int i = 0; i < 8; i++)
                    zz[i] = *reinterpret_cast<const unsigned long long*>(
                        &z_dup[kk][2 * (ty + 16 * i)]);
                #pragma unroll
                for (int j = 0; j < 4; j++)
                    ef[j] = *reinterpret_cast<const unsigned long long*>(
                        &e_s[kk][2 * tx + 32 * j]);
                #pragma unroll
                for (int i = 0; i < 8; i++)
                    #pragma unroll
                    for (int j = 0; j < 4; j++)
                        FFMA2(acc[i][j], zz[i], ef[j]);
            }
        }

        // scores + running argmin (ascending k scan; ties -> smallest k)
        float2 esq2[4];
        #pragma unroll
        for (int j = 0; j < 4; j++)
            esq2[j] = *reinterpret_cast<const float2*>(&g_esq[k0 + 2 * tx + 32 * j]);

        #pragma unroll
        for (int i = 0; i < 8; i++) {
            float bs = 3.4e38f; int bk = 0x7fffffff;
            #pragma unroll
            for (int j = 0; j < 4; j++) {
                float2 a = *reinterpret_cast<float2*>(&acc[i][j]);
                int kc = k0 + 2 * tx + 32 * j;
                // s = fl( fl(zsq - 2*dot) + esq ) -- intrinsics forbid FMA fusion
                float s0 = __fadd_rn(__fsub_rn(zsqv[i], __fmul_rn(2.0f, a.x)), esq2[j].x);
                float s1 = __fadd_rn(__fsub_rn(zsqv[i], __fmul_rn(2.0f, a.y)), esq2[j].y);
                if (s0 < bs || (s0 == bs && kc < bk))       { bs = s0; bk = kc; }
                if (s1 < bs || (s1 == bs && (kc + 1) < bk)) { bs = s1; bk = kc + 1; }
            }
            #pragma unroll
            for (int off = 8; off; off >>= 1) {   // reduce over tx (same ty half-warp)
                float os = __shfl_xor_sync(0xffffffffu, bs, off);
                int   ok = __shfl_xor_sync(0xffffffffu, bk, off);
                if (os < bs || (os == bs && ok < bk)) { bs = os; bk = ok; }
            }
            if (tx == 0) {
                int r = ty + 16 * i;
                if (bs < best_s[r] || (bs == best_s[r] && bk < best_k[r])) {
                    best_s[r] = bs; best_k[r] = bk;
                }
            }
        }
    }
    __syncthreads();
    if (tid < 128) g_idx[n0 + tid] = best_k[tid];
}

// ---------------------------------------------------------------------------
// Gather z_q, straight-through output, commitment loss, segment sums.
// Element order e = d*32768 + n  (n fastest -> coalesced z / out access).
// ---------------------------------------------------------------------------
__global__ void k_gather(const float* __restrict__ z, const float* __restrict__ emb,
                         float* __restrict__ out) {
    float* out_zq  = out + OFF_ZQ;
    float* out_idx = out + OFF_IDX;
    int tid0 = blockIdx.x * blockDim.x + threadIdx.x;
    int stride = gridDim.x * blockDim.x;
    double lsum = 0.0;
    for (int e = tid0; e < N_TOT * DIM; e += stride) {
        int d = e >> 15;         // /32768
        int n = e & 32767;
        int idx = g_idx[n];
        float zq = emb[idx * DIM + d];
        int b = n >> 10, hw = n & 1023;
        int za = b * (DIM * HW) + d * HW + hw;
        float zv = z[za];
        out_zq[za] = __fadd_rn(zv, __fsub_rn(zq, zv));   // straight-through, 2 roundings
        float df = __fsub_rn(zv, zq);
        lsum += (double)df * (double)df;
        atomicAdd(&g_embed_sum[idx * DIM + d], zv);
        if (d == 0) {
            atomicAdd(&g_counts[idx], 1.0f);
            out_idx[n] = (float)idx;
        }
    }
    // block-reduce loss, one atomic per block
    #pragma unroll
    for (int o = 16; o; o >>= 1) lsum += __shfl_xor_sync(0xffffffffu, lsum, o);
    __shared__ double ws[8];
    int lane = threadIdx.x & 31, warp = threadIdx.x >> 5;
    if (lane == 0) ws[warp] = lsum;
    __syncthreads();
    if (threadIdx.x == 0) {
        double t = 0.0;
        #pragma unroll
        for (int w = 0; w < 8; w++) t += ws[w];
        atomicAdd(&g_loss, t);
    }
}

// ---------------------------------------------------------------------------
// Finalize cluster sizes (1 block of 1024) + loss scalar
// ---------------------------------------------------------------------------
__global__ void k_fin1(const float* __restrict__ ema_cs, float* __restrict__ out) {
    __shared__ float red[1024];
    int k = threadIdx.x;
    const float decay = 0.99f;
    const float one_minus = (float)(1.0 - 0.99);
    float nc = decay * ema_cs[k] + one_minus * g_counts[k];
    red[k] = nc;
    __syncthreads();
    for (int s = 512; s; s >>= 1) {
        if (k < s) red[k] += red[k + s];
        __syncthreads();
    }
    float n = red[0];
    float cs = (nc + 1e-5f) / (n + (float)KCODE * 1e-5f) * n;
    g_cluster_size[k] = cs;
    out[OFF_NCS + k] = nc;
    if (k == 0) out[OFF_LOSS] = (float)(g_loss * (1.0 / 8388608.0));
}

// ---------------------------------------------------------------------------
// Finalize EMA embed sum + new embedding
// ---------------------------------------------------------------------------
__global__ void k_fin2(const float* __restrict__ ema_es, float* __restrict__ out) {
    int i = blockIdx.x * blockDim.x + threadIdx.x;
    if (i >= KCODE * DIM) return;
    const float decay = 0.99f;
    const float one_minus = (float)(1.0 - 0.99);
    float nes = decay * ema_es[i] + one_minus * g_embed_sum[i];
    out[OFF_NES + i] = nes;
    out[OFF_NEMB + i] = nes / g_cluster_size[i >> 8];   // i>>8 = k (DIM=256)
}

// ---------------------------------------------------------------------------
extern "C" void kernel_launch(void* const* d_in, const int* in_sizes, int n_in,
                              void* d_out, int out_size) {
    const float* z      = (const float*)d_in[0];   // (32,256,32,32)
    const float* emb    = (const float*)d_in[1];   // (1024,256)
    const float* ema_cs = (const float*)d_in[2];   // (1024,)
    const float* ema_es = (const float*)d_in[3];   // (1024,256)
    float* out = (float*)d_out;

    k_zero  <<<(KCODE * DIM + 255) / 256 + 1, 256>>>();
    k_esq   <<<KCODE / 8, 256>>>(emb);
    k_zsq   <<<N_TOT / 256, 256>>>(z);
    k_argmin<<<N_TOT / 128, 256>>>(z, emb);
    k_gather<<<2048, 256>>>(z, emb, out);
    k_fin1  <<<1, 1024>>>(ema_cs, out);
    k_fin2  <<<KCODE * DIM / 256, 256>>>(ema_es, out);
}